// round 14
// baseline (speedup 1.0000x reference)
#include <cuda_runtime.h>
#include <math.h>

#define T_   1024
#define B_   32
#define IN_  1024
#define H_   512
#define TB_  (T_ * B_)

typedef unsigned long long ull;

// ---------------- static device scratch (no runtime alloc allowed) ----------
__device__ float g_xin[2][(size_t)TB_ * H_];   // per-direction input projections (biases folded)
__device__ float g_seq[(size_t)TB_ * 2 * H_];  // layer-0 output, [t][b][2H]

// ---------------- helpers ----------------
__device__ __forceinline__ unsigned smem_u32(const void* p) {
    unsigned a;
    asm("{ .reg .u64 t; cvta.to.shared.u64 t, %1; cvt.u32.u64 %0, t; }" : "=r"(a) : "l"(p));
    return a;
}
// DSMEM push: map local smem addr to peer rank, scalar store
__device__ __forceinline__ void dsmem_st(unsigned laddr, unsigned rank, float v) {
    asm volatile(
        "{\n\t.reg .u32 ra;\n\t"
        "mapa.shared::cluster.u32 ra, %0, %1;\n\t"
        "st.shared::cluster.f32 [ra], %2;\n\t}"
        :: "r"(laddr), "r"(rank), "f"(v) : "memory");
}
// f32x2 helpers (recur kernel)
__device__ __forceinline__ void upk2(ull v, float& lo, float& hi) {
    asm("mov.b64 {%0,%1}, %2;" : "=f"(lo), "=f"(hi) : "l"(v));
}
__device__ __forceinline__ void fma2(ull& d, ull a, ull b) {
    asm("fma.rn.f32x2 %0, %1, %2, %0;" : "+l"(d) : "l"(a), "l"(b));
}
// exact tf32 split: a = hi + lo, hi tf32-representable
__device__ __forceinline__ void split_tf32(float a, float& hi, float& lo) {
    unsigned u;
    asm("cvt.rna.tf32.f32 %0, %1;" : "=r"(u) : "f"(a));
    hi = __uint_as_float(u);
    lo = a - hi;
}
// m16n8k8 tf32 MMA, accumulate in-place
__device__ __forceinline__ void mma_tf32(float* c,
    unsigned a0, unsigned a1, unsigned a2, unsigned a3,
    unsigned b0, unsigned b1)
{
    asm volatile(
        "mma.sync.aligned.m16n8k8.row.col.f32.tf32.tf32.f32 "
        "{%0,%1,%2,%3}, {%4,%5,%6,%7}, {%8,%9}, {%0,%1,%2,%3};"
        : "+f"(c[0]), "+f"(c[1]), "+f"(c[2]), "+f"(c[3])
        : "r"(a0), "r"(a1), "r"(a2), "r"(a3), "r"(b0), "r"(b1));
}

// ---------------------------------------------------------------------------
// Input-projection GEMM v2: 3xTF32 tensor-core path.
//   g_xin[cell][m][n] = sum_k A[m][k]*noise_in[c][b][k]*w_ih[c][n][k]
//                       + b_ih[c][n] + b_hh[c][n],   m = t*B + b
// A is split a = ahi + alo (exact); result = ahi*bhi + ahi*blo + alo*bhi.
// Tile BM=128, BN=64, BK=16; 8 warps as 4m x 2n; warp tile 32x32
// (2 m16 x 4 n8 frags), 32 fp32 accumulators per thread.
// smem: [k][m] stride 136 and [k][n] stride 72 -> conflict-free frag fetch.
// ---------------------------------------------------------------------------
__global__ __launch_bounds__(256, 2) void gemm_kernel(
    const float* __restrict__ x,
    const float* __restrict__ w_ih,
    const float* __restrict__ b_ih,
    const float* __restrict__ b_hh,
    const float* __restrict__ noise_in,
    int layer)
{
    __shared__ float Ah[16 * 136];   // [k][m] hi
    __shared__ float Al[16 * 136];   // [k][m] lo
    __shared__ float Bh[16 * 72];    // [k][n] hi
    __shared__ float Bl[16 * 72];    // [k][n] lo

    const int tid  = threadIdx.x;
    const int cell = blockIdx.z;
    const int cabs = layer * 2 + cell;
    const int n0   = blockIdx.x * 64;
    const int m0   = blockIdx.y * 128;
    const int wid  = tid >> 5;
    const int lane = tid & 31;
    const int wm   = (wid >> 1) * 32;        // warp m offset (0,32,64,96)
    const int wn   = (wid & 1) * 32;         // warp n offset (0,32)
    const int g    = lane >> 2;              // group 0..7
    const int tq   = lane & 3;               // thread-in-group 0..3

    const float* A  = (layer == 0) ? x : g_seq;
    const float* nz = noise_in + (size_t)cabs * B_ * IN_;
    const float* wb = w_ih + (size_t)cabs * H_ * IN_;
    float* outp = g_xin[cell];

    float acc[2][4][4];
#pragma unroll
    for (int i = 0; i < 2; i++)
#pragma unroll
        for (int j = 0; j < 4; j++)
#pragma unroll
            for (int q = 0; q < 4; q++) acc[i][j][q] = 0.0f;

    // ---- loaders (same gmem addressing as the proven fp32 version) ----
    const int e0 = tid, e1 = tid + 256;
    const int row0 = e0 >> 2, kq0 = (e0 & 3) * 4;
    const int row1 = e1 >> 2, kq1 = (e1 & 3) * 4;
    size_t ab0, ab1;
    if (layer == 0) {   // m = t*B + b ; x addr = b*(T*IN) + t*IN
        ab0 = (size_t)(row0 & 31) * ((size_t)T_ * IN_) + (size_t)(m0 / 32 + (row0 >> 5)) * IN_;
        ab1 = (size_t)(row1 & 31) * ((size_t)T_ * IN_) + (size_t)(m0 / 32 + (row1 >> 5)) * IN_;
    } else {
        ab0 = (size_t)(m0 + row0) * IN_;
        ab1 = (size_t)(m0 + row1) * IN_;
    }
    const size_t nb0 = (size_t)(row0 & 31) * IN_;
    const size_t nb1 = (size_t)(row1 & 31) * IN_;
    const int brow = tid >> 2, bkq = (tid & 3) * 4;
    const float* wrow = wb + (size_t)(n0 + brow) * IN_ + bkq;

    float4 xv0 = *(const float4*)(A + ab0 + kq0);
    float4 nv0 = *(const float4*)(nz + nb0 + kq0);
    float4 xv1 = *(const float4*)(A + ab1 + kq1);
    float4 nv1 = *(const float4*)(nz + nb1 + kq1);
    float4 wv0 = *(const float4*)(wrow);

    for (int k0 = 0; k0 < IN_; k0 += 16) {
        // stage current tile (split hi/lo)
        {
            float av[4] = { xv0.x * nv0.x, xv0.y * nv0.y, xv0.z * nv0.z, xv0.w * nv0.w };
#pragma unroll
            for (int j = 0; j < 4; j++) {
                float hi, lo; split_tf32(av[j], hi, lo);
                Ah[(kq0 + j) * 136 + row0] = hi;
                Al[(kq0 + j) * 136 + row0] = lo;
            }
            float aw[4] = { xv1.x * nv1.x, xv1.y * nv1.y, xv1.z * nv1.z, xv1.w * nv1.w };
#pragma unroll
            for (int j = 0; j < 4; j++) {
                float hi, lo; split_tf32(aw[j], hi, lo);
                Ah[(kq1 + j) * 136 + row1] = hi;
                Al[(kq1 + j) * 136 + row1] = lo;
            }
            float bv[4] = { wv0.x, wv0.y, wv0.z, wv0.w };
#pragma unroll
            for (int j = 0; j < 4; j++) {
                float hi, lo; split_tf32(bv[j], hi, lo);
                Bh[(bkq + j) * 72 + brow] = hi;
                Bl[(bkq + j) * 72 + brow] = lo;
            }
        }
        __syncthreads();

        // prefetch next tile's gmem loads (overlap with MMA below)
        const int kn = k0 + 16;
        if (kn < IN_) {
            xv0 = *(const float4*)(A + ab0 + kn + kq0);
            nv0 = *(const float4*)(nz + nb0 + kn + kq0);
            xv1 = *(const float4*)(A + ab1 + kn + kq1);
            nv1 = *(const float4*)(nz + nb1 + kn + kq1);
            wv0 = *(const float4*)(wrow + kn);
        }

#pragma unroll
        for (int ks = 0; ks < 16; ks += 8) {
            // B fragments: b0 k=ks+tq, b1 k=ks+tq+4, n = wn + nt*8 + g
            unsigned bhf[4][2], blf[4][2];
#pragma unroll
            for (int nt = 0; nt < 4; nt++) {
                const int nn = wn + nt * 8 + g;
                bhf[nt][0] = __float_as_uint(Bh[(ks + tq) * 72 + nn]);
                bhf[nt][1] = __float_as_uint(Bh[(ks + tq + 4) * 72 + nn]);
                blf[nt][0] = __float_as_uint(Bl[(ks + tq) * 72 + nn]);
                blf[nt][1] = __float_as_uint(Bl[(ks + tq + 4) * 72 + nn]);
            }
#pragma unroll
            for (int mt = 0; mt < 2; mt++) {
                const int r = wm + mt * 16;
                // A fragments (row-major): a0(r+g, tq) a1(r+g+8, tq)
                //                          a2(r+g, tq+4) a3(r+g+8, tq+4)
                unsigned ah0 = __float_as_uint(Ah[(ks + tq) * 136 + r + g]);
                unsigned ah1 = __float_as_uint(Ah[(ks + tq) * 136 + r + g + 8]);
                unsigned ah2 = __float_as_uint(Ah[(ks + tq + 4) * 136 + r + g]);
                unsigned ah3 = __float_as_uint(Ah[(ks + tq + 4) * 136 + r + g + 8]);
                unsigned al0 = __float_as_uint(Al[(ks + tq) * 136 + r + g]);
                unsigned al1 = __float_as_uint(Al[(ks + tq) * 136 + r + g + 8]);
                unsigned al2 = __float_as_uint(Al[(ks + tq + 4) * 136 + r + g]);
                unsigned al3 = __float_as_uint(Al[(ks + tq + 4) * 136 + r + g + 8]);
#pragma unroll
                for (int nt = 0; nt < 4; nt++) {
                    mma_tf32(acc[mt][nt], ah0, ah1, ah2, ah3, bhf[nt][0], bhf[nt][1]);
                    mma_tf32(acc[mt][nt], ah0, ah1, ah2, ah3, blf[nt][0], blf[nt][1]);
                    mma_tf32(acc[mt][nt], al0, al1, al2, al3, bhf[nt][0], bhf[nt][1]);
                }
            }
        }
        __syncthreads();
    }

    // Epilogue: c0(rg, 2tq) c1(rg, 2tq+1) c2(rg+8, 2tq) c3(rg+8, 2tq+1)
#pragma unroll
    for (int nt = 0; nt < 4; nt++) {
        const int col = n0 + wn + nt * 8 + 2 * tq;
        const float bi0 = b_ih[cabs * H_ + col]     + b_hh[cabs * H_ + col];
        const float bi1 = b_ih[cabs * H_ + col + 1] + b_hh[cabs * H_ + col + 1];
#pragma unroll
        for (int mt = 0; mt < 2; mt++) {
            const int r0 = m0 + wm + mt * 16 + g;
            float2 v0 = make_float2(acc[mt][nt][0] + bi0, acc[mt][nt][1] + bi1);
            float2 v1 = make_float2(acc[mt][nt][2] + bi0, acc[mt][nt][3] + bi1);
            *(float2*)(outp + (size_t)r0 * H_ + col)       = v0;
            *(float2*)(outp + (size_t)(r0 + 8) * H_ + col) = v1;
        }
    }
}

// ---------------------------------------------------------------------------
// Recurrent scan — EXACT R9 structure (best measured: 3.73ms/launch).
// 16 clusters of 8 CTAs; CTA owns 4 batches x 64 h-cols; W_hh register-
// resident; per-step: FMA on local hbuf -> red2 smem reduction (1 sync) ->
// per-thread epilogue (b=kp,h): tanh, local write + 7 DSMEM pushes + STG ->
// combined cluster arrive+wait.
// ---------------------------------------------------------------------------
__global__ __launch_bounds__(256, 1) __cluster_dims__(8, 1, 1)
void recur_kernel(
    const float* __restrict__ w_hh,
    const float* __restrict__ noise_h,
    const float* __restrict__ mask,
    float* __restrict__ out,      // d_out: [B,T,2H] (layer 1 writes here)
    float* __restrict__ hn,       // d_out + B*T*2H: [L*D,B,H]
    int layer)
{
    __shared__ float hbuf[2][4 * 512];        // full h*nh vector, double buffered (16KB)
    __shared__ float red2[4][4][64];          // [kp][b][hl] split-K partials (4KB)

    const int tid  = threadIdx.x;
    const int bx   = blockIdx.x;
    const int dir  = bx >> 6;                 // 0 fwd, 1 bwd
    const int rank = bx & 7;                  // cluster rank == h-slice
    const int grp  = (bx >> 3) & 7;           // batch group
    const int b0   = grp * 4;
    const int h0   = rank * 64;
    const int kp   = tid >> 6;                // K partition AND owned batch b
    const int hl   = tid & 63;
    const int h    = h0 + hl;
    const int c    = layer * 2 + dir;

    const unsigned hb_a = smem_u32(&hbuf[0][0]);

    // W_hh slice into registers as aligned f32x2 pairs: w[h][kp*128 .. +127]
    union F4U2 { float4 f; ulonglong2 u; };
    ulonglong2 wu[32];
    {
        const float4* wp = (const float4*)(w_hh + ((size_t)c * H_ + h) * H_ + kp * 128);
#pragma unroll
        for (int i = 0; i < 32; i++) { F4U2 t; t.f = wp[i]; wu[i] = t.u; }
    }

    // per-thread recurrent state for output (b=kp, h)
    const float nh = noise_h[((size_t)c * B_ + b0 + kp) * H_ + h];
    float hprev = 0.0f;
    const float* xin = g_xin[dir];
    const unsigned my_off = (unsigned)(kp * 512 + h) * 4u;

    for (int t = 0; t < T_; t++) {
        const int ta = dir ? (T_ - 1 - t) : t;

        // prefetch xin + mask (off the critical path)
        const float xv = __ldg(xin + ((size_t)ta * B_ + b0 + kp) * H_ + h);
        const float mt = __ldg(mask + (size_t)(b0 + kp) * T_ + ta);

        // dot products over our K slice, reading LOCAL hbuf (broadcast LDS.128)
        ull acc[4] = {0ull, 0ull, 0ull, 0ull};
        if (t > 0) {
            const float4* hb = (const float4*)&hbuf[t & 1][0];
#pragma unroll
            for (int i = 0; i < 32; i++) {
                ulonglong2 w2 = wu[i];
#pragma unroll
                for (int b = 0; b < 4; b++) {
                    F4U2 q; q.f = hb[b * 128 + kp * 32 + i];
                    fma2(acc[b], q.u.x, w2.x);
                    fma2(acc[b], q.u.y, w2.y);
                }
            }
        }
#pragma unroll
        for (int b = 0; b < 4; b++) {
            float lo, hi; upk2(acc[b], lo, hi);
            red2[kp][b][hl] = lo + hi;
        }
        __syncthreads();

        // epilogue: every thread finishes ONE output (b=kp, h)
        {
            const float rec = red2[0][kp][hl] + red2[1][kp][hl]
                            + red2[2][kp][hl] + red2[3][kp][hl];
            const float hnew = tanhf(xv + rec);           // biases folded in xin
            const float hcur = hnew * mt + hprev * (1.0f - mt);
            hprev = hcur;
            const float v = hcur * nh;
            const int nb = (t + 1) & 1;
            hbuf[nb][kp * 512 + h] = v;                   // own slice, local
            const unsigned dst = hb_a + (unsigned)(nb * 8192) + my_off;
#pragma unroll
            for (unsigned r = 0; r < 8; r++)
                if (r != (unsigned)rank) dsmem_st(dst, r, v);
            if (layer == 0)
                g_seq[((size_t)ta * B_ + b0 + kp) * 1024 + dir * 512 + h] = hcur;
            else
                out[((size_t)(b0 + kp) * T_ + ta) * 1024 + dir * 512 + h] = hcur;
        }

        // one hardware cluster barrier per step: orders remote stores
        // (release) and gates every CTA's next step (acquire).
        asm volatile("barrier.cluster.arrive.aligned;" ::: "memory");
        asm volatile("barrier.cluster.wait.aligned;"   ::: "memory");
    }

    // final hidden states (after last barrier: no more remote traffic)
    hn[((size_t)c * B_ + b0 + kp) * H_ + h] = hprev;
}

// ---------------------------------------------------------------------------
extern "C" void kernel_launch(void* const* d_in, const int* in_sizes, int n_in,
                              void* d_out, int out_size) {
    const float* x        = (const float*)d_in[0];
    const float* mask     = (const float*)d_in[1];
    const float* w_ih     = (const float*)d_in[2];
    const float* w_hh     = (const float*)d_in[3];
    const float* b_ih     = (const float*)d_in[4];
    const float* b_hh     = (const float*)d_in[5];
    const float* noise_in = (const float*)d_in[6];
    const float* noise_h  = (const float*)d_in[7];
    float* out = (float*)d_out;                       // [B,T,2H]
    float* hn  = out + (size_t)B_ * T_ * 2 * H_;      // [L*D,B,H]

    dim3 gg(H_ / 64, TB_ / 128, 2);                   // (8, 256, 2)

    gemm_kernel<<<gg, 256>>>(x, w_ih, b_ih, b_hh, noise_in, 0);
    recur_kernel<<<128, 256>>>(w_hh, noise_h, mask, out, hn, 0);
    gemm_kernel<<<gg, 256>>>(x, w_ih, b_ih, b_hh, noise_in, 1);
    recur_kernel<<<128, 256>>>(w_hh, noise_h, mask, out, hn, 1);
}

// round 15
// speedup vs baseline: 1.6855x; 1.6855x over previous
#include <cuda_runtime.h>
#include <math.h>

#define T_   1024
#define B_   32
#define IN_  1024
#define H_   512
#define TB_  (T_ * B_)

typedef unsigned long long ull;

// ---------------- static device scratch (no runtime alloc allowed) ----------
__device__ float g_xin[2][(size_t)TB_ * H_];   // per-direction input projections (biases folded)
__device__ float g_seq[(size_t)TB_ * 2 * H_];  // layer-0 output, [t][b][2H]

// ---------------- f32x2 helpers (ptxas never emits FFMA2 from C++) ----------
__device__ __forceinline__ ull pk2(float lo, float hi) {
    ull r; asm("mov.b64 %0, {%1,%2};" : "=l"(r) : "f"(lo), "f"(hi)); return r;
}
__device__ __forceinline__ void upk2(ull v, float& lo, float& hi) {
    asm("mov.b64 {%0,%1}, %2;" : "=f"(lo), "=f"(hi) : "l"(v));
}
__device__ __forceinline__ void fma2(ull& d, ull a, ull b) {
    asm("fma.rn.f32x2 %0, %1, %2, %0;" : "+l"(d) : "l"(a), "l"(b));
}
__device__ __forceinline__ unsigned smem_u32(const void* p) {
    unsigned a;
    asm("{ .reg .u64 t; cvta.to.shared.u64 t, %1; cvt.u32.u64 %0, t; }" : "=r"(a) : "l"(p));
    return a;
}
// DSMEM 16B push to peer rank
__device__ __forceinline__ void dsmem_st_v4(unsigned laddr, unsigned rank, float4 q) {
    asm volatile(
        "{\n\t.reg .u32 ra;\n\t"
        "mapa.shared::cluster.u32 ra, %0, %1;\n\t"
        "st.shared::cluster.v4.f32 [ra], {%2,%3,%4,%5};\n\t}"
        :: "r"(laddr), "r"(rank), "f"(q.x), "f"(q.y), "f"(q.z), "f"(q.w) : "memory");
}

// ---------------------------------------------------------------------------
// Input-projection GEMM (register-prefetch pipelined f32x2) — proven (R7-R9).
//   g_xin[cell][m][n] = sum_k A[m][k]*noise_in[c][b][k]*w_ih[c][n][k]
//                       + b_ih[c][n] + b_hh[c][n],   m = t*B + b
// ---------------------------------------------------------------------------
__global__ __launch_bounds__(256, 2) void gemm_kernel(
    const float* __restrict__ x,
    const float* __restrict__ w_ih,
    const float* __restrict__ b_ih,
    const float* __restrict__ b_hh,
    const float* __restrict__ noise_in,
    int layer)
{
    __shared__ float As[16 * 132];   // [k][m], padded
    __shared__ float Bs[16 * 68];    // [k][n], padded

    const int tid  = threadIdx.x;
    const int cell = blockIdx.z;
    const int cabs = layer * 2 + cell;
    const int n0   = blockIdx.x * 64;
    const int m0   = blockIdx.y * 128;
    const int tx   = tid & 15;
    const int ty   = tid >> 4;
    const int msub = ty * 8;
    const int nsub = tx * 4;

    const float* A  = (layer == 0) ? x : g_seq;
    const float* nz = noise_in + (size_t)cabs * B_ * IN_;
    const float* wb = w_ih + (size_t)cabs * H_ * IN_;
    float* outp = g_xin[cell];

    ull acc[4][4];
#pragma unroll
    for (int i = 0; i < 4; i++)
#pragma unroll
        for (int j = 0; j < 4; j++) acc[i][j] = 0ull;

    const int e0 = tid, e1 = tid + 256;
    const int row0 = e0 >> 2, kq0 = (e0 & 3) * 4;
    const int row1 = e1 >> 2, kq1 = (e1 & 3) * 4;
    size_t ab0, ab1;
    if (layer == 0) {   // m = t*B + b ; x addr = b*(T*IN) + t*IN
        ab0 = (size_t)(row0 & 31) * ((size_t)T_ * IN_) + (size_t)(m0 / 32 + (row0 >> 5)) * IN_;
        ab1 = (size_t)(row1 & 31) * ((size_t)T_ * IN_) + (size_t)(m0 / 32 + (row1 >> 5)) * IN_;
    } else {
        ab0 = (size_t)(m0 + row0) * IN_;
        ab1 = (size_t)(m0 + row1) * IN_;
    }
    const size_t nb0 = (size_t)(row0 & 31) * IN_;
    const size_t nb1 = (size_t)(row1 & 31) * IN_;
    const int brow = tid >> 2, bkq = (tid & 3) * 4;
    const float* wrow = wb + (size_t)(n0 + brow) * IN_ + bkq;

    float4 xv0 = *(const float4*)(A + ab0 + kq0);
    float4 nv0 = *(const float4*)(nz + nb0 + kq0);
    float4 xv1 = *(const float4*)(A + ab1 + kq1);
    float4 nv1 = *(const float4*)(nz + nb1 + kq1);
    float4 wv0 = *(const float4*)(wrow);

    for (int k0 = 0; k0 < IN_; k0 += 16) {
        As[(kq0 + 0) * 132 + row0] = xv0.x * nv0.x;
        As[(kq0 + 1) * 132 + row0] = xv0.y * nv0.y;
        As[(kq0 + 2) * 132 + row0] = xv0.z * nv0.z;
        As[(kq0 + 3) * 132 + row0] = xv0.w * nv0.w;
        As[(kq1 + 0) * 132 + row1] = xv1.x * nv1.x;
        As[(kq1 + 1) * 132 + row1] = xv1.y * nv1.y;
        As[(kq1 + 2) * 132 + row1] = xv1.z * nv1.z;
        As[(kq1 + 3) * 132 + row1] = xv1.w * nv1.w;
        Bs[(bkq + 0) * 68 + brow] = wv0.x;
        Bs[(bkq + 1) * 68 + brow] = wv0.y;
        Bs[(bkq + 2) * 68 + brow] = wv0.z;
        Bs[(bkq + 3) * 68 + brow] = wv0.w;
        __syncthreads();

        const int kn = k0 + 16;
        if (kn < IN_) {
            xv0 = *(const float4*)(A + ab0 + kn + kq0);
            nv0 = *(const float4*)(nz + nb0 + kn + kq0);
            xv1 = *(const float4*)(A + ab1 + kn + kq1);
            nv1 = *(const float4*)(nz + nb1 + kn + kq1);
            wv0 = *(const float4*)(wrow + kn);
        }

#pragma unroll
        for (int k = 0; k < 16; k++) {
            float4 b4 = *(const float4*)&Bs[k * 68 + nsub];
            ull bd0 = pk2(b4.x, b4.x);
            ull bd1 = pk2(b4.y, b4.y);
            ull bd2 = pk2(b4.z, b4.z);
            ull bd3 = pk2(b4.w, b4.w);
#pragma unroll
            for (int mp = 0; mp < 4; mp++) {
                ull au = *(const ull*)&As[k * 132 + msub + 2 * mp];
                fma2(acc[mp][0], au, bd0);
                fma2(acc[mp][1], au, bd1);
                fma2(acc[mp][2], au, bd2);
                fma2(acc[mp][3], au, bd3);
            }
        }
        __syncthreads();
    }

    float bi[4];
#pragma unroll
    for (int nn = 0; nn < 4; nn++) {
        int n = n0 + nsub + nn;
        bi[nn] = b_ih[cabs * H_ + n] + b_hh[cabs * H_ + n];
    }
#pragma unroll
    for (int mp = 0; mp < 4; mp++) {
        float lo[4], hi[4];
#pragma unroll
        for (int nn = 0; nn < 4; nn++) upk2(acc[mp][nn], lo[nn], hi[nn]);
        float4 v0 = make_float4(lo[0] + bi[0], lo[1] + bi[1], lo[2] + bi[2], lo[3] + bi[3]);
        float4 v1 = make_float4(hi[0] + bi[0], hi[1] + bi[1], hi[2] + bi[2], hi[3] + bi[3]);
        size_t r0 = (size_t)(m0 + msub + 2 * mp) * H_ + n0 + nsub;
        *(float4*)(outp + r0)      = v0;
        *(float4*)(outp + r0 + H_) = v1;
    }
}

// ---------------------------------------------------------------------------
// Recurrent scan v8: R9 structure with COALESCED v4 pushes.
// 16 clusters of 8 CTAs; CTA owns 4 batches x 64 h-cols; W_hh register-
// resident. Per step: FMA on local hbuf -> red2 reduction (sync) -> epilogue
// (each thread: tanh, local hbuf write, STG) -> sync -> 64 pusher threads
// read the CTA's 256-float production as float4 and push to all 8 ranks
// (512 remote stores/CTA/step instead of 1792) -> cluster arrive+wait.
// ---------------------------------------------------------------------------
__global__ __launch_bounds__(256, 1) __cluster_dims__(8, 1, 1)
void recur_kernel(
    const float* __restrict__ w_hh,
    const float* __restrict__ noise_h,
    const float* __restrict__ mask,
    float* __restrict__ out,      // d_out: [B,T,2H] (layer 1 writes here)
    float* __restrict__ hn,       // d_out + B*T*2H: [L*D,B,H]
    int layer)
{
    __shared__ float hbuf[2][4 * 512];        // full h*nh vector, double buffered (16KB)
    __shared__ float red2[4][4][64];          // [kp][b][hl] split-K partials (4KB)

    const int tid  = threadIdx.x;
    const int bx   = blockIdx.x;
    const int dir  = bx >> 6;                 // 0 fwd, 1 bwd
    const int rank = bx & 7;                  // cluster rank == h-slice
    const int grp  = (bx >> 3) & 7;           // batch group
    const int b0   = grp * 4;
    const int h0   = rank * 64;
    const int kp   = tid >> 6;                // K partition AND owned batch b
    const int hl   = tid & 63;
    const int h    = h0 + hl;
    const int c    = layer * 2 + dir;

    const unsigned hb_a = smem_u32(&hbuf[0][0]);

    // W_hh slice into registers as aligned f32x2 pairs: w[h][kp*128 .. +127]
    union F4U2 { float4 f; ulonglong2 u; };
    ulonglong2 wu[32];
    {
        const float4* wp = (const float4*)(w_hh + ((size_t)c * H_ + h) * H_ + kp * 128);
#pragma unroll
        for (int i = 0; i < 32; i++) { F4U2 t; t.f = wp[i]; wu[i] = t.u; }
    }

    // per-thread recurrent state for output (b=kp, h)
    const float nh = noise_h[((size_t)c * B_ + b0 + kp) * H_ + h];
    float hprev = 0.0f;
    const float* xin = g_xin[dir];

    // pusher mapping (tid < 64): float4 #tid of the CTA's production region
    const int pb = tid >> 4;                  // batch 0..3
    const int pj = tid & 15;                  // 16B chunk within 64-float slice
    const unsigned push_off = (unsigned)(pb * 512 + h0 + pj * 4) * 4u;

    for (int t = 0; t < T_; t++) {
        const int ta = dir ? (T_ - 1 - t) : t;

        // prefetch xin + mask (off the critical path)
        const float xv = __ldg(xin + ((size_t)ta * B_ + b0 + kp) * H_ + h);
        const float mt = __ldg(mask + (size_t)(b0 + kp) * T_ + ta);

        // dot products over our K slice, reading LOCAL hbuf (broadcast LDS.128)
        ull acc[4] = {0ull, 0ull, 0ull, 0ull};
        if (t > 0) {
            const float4* hb = (const float4*)&hbuf[t & 1][0];
#pragma unroll
            for (int i = 0; i < 32; i++) {
                ulonglong2 w2 = wu[i];
#pragma unroll
                for (int b = 0; b < 4; b++) {
                    F4U2 q; q.f = hb[b * 128 + kp * 32 + i];
                    fma2(acc[b], q.u.x, w2.x);
                    fma2(acc[b], q.u.y, w2.y);
                }
            }
        }
#pragma unroll
        for (int b = 0; b < 4; b++) {
            float lo, hi; upk2(acc[b], lo, hi);
            red2[kp][b][hl] = lo + hi;
        }
        __syncthreads();

        // epilogue: every thread finishes ONE output (b=kp, h)
        const int nb = (t + 1) & 1;
        {
            const float rec = red2[0][kp][hl] + red2[1][kp][hl]
                            + red2[2][kp][hl] + red2[3][kp][hl];
            const float z    = xv + rec;                  // biases folded in xin
            const float e    = __expf(2.0f * z);          // saturates correctly
            const float hnew = 1.0f - __fdividef(2.0f, e + 1.0f);
            const float hcur = hnew * mt + hprev * (1.0f - mt);
            hprev = hcur;
            hbuf[nb][kp * 512 + h] = hcur * nh;           // own slice, local
            if (layer == 0)
                g_seq[((size_t)ta * B_ + b0 + kp) * 1024 + dir * 512 + h] = hcur;
            else
                out[((size_t)(b0 + kp) * T_ + ta) * 1024 + dir * 512 + h] = hcur;
        }
        __syncthreads();   // production visible to pusher threads

        // coalesced push: 64 threads x 1 float4 x 8 ranks = 512 remote stores
        if (tid < 64) {
            const unsigned src = hb_a + (unsigned)(nb * 8192) + push_off;
            const float4 v = *(const float4*)((const char*)hbuf + (size_t)(nb * 8192) + push_off);
#pragma unroll
            for (unsigned r = 0; r < 8; r++)
                dsmem_st_v4(src, r, v);   // self-push overwrites same value
        }

        // one hardware cluster barrier per step: orders remote stores
        // (release) and gates every CTA's next step (acquire).
        asm volatile("barrier.cluster.arrive.aligned;" ::: "memory");
        asm volatile("barrier.cluster.wait.aligned;"   ::: "memory");
    }

    // final hidden states (after last barrier: no more remote traffic)
    hn[((size_t)c * B_ + b0 + kp) * H_ + h] = hprev;
}

// ---------------------------------------------------------------------------
extern "C" void kernel_launch(void* const* d_in, const int* in_sizes, int n_in,
                              void* d_out, int out_size) {
    const float* x        = (const float*)d_in[0];
    const float* mask     = (const float*)d_in[1];
    const float* w_ih     = (const float*)d_in[2];
    const float* w_hh     = (const float*)d_in[3];
    const float* b_ih     = (const float*)d_in[4];
    const float* b_hh     = (const float*)d_in[5];
    const float* noise_in = (const float*)d_in[6];
    const float* noise_h  = (const float*)d_in[7];
    float* out = (float*)d_out;                       // [B,T,2H]
    float* hn  = out + (size_t)B_ * T_ * 2 * H_;      // [L*D,B,H]

    dim3 gg(H_ / 64, TB_ / 128, 2);                   // (8, 256, 2)

    gemm_kernel<<<gg, 256>>>(x, w_ih, b_ih, b_hh, noise_in, 0);
    recur_kernel<<<128, 256>>>(w_hh, noise_h, mask, out, hn, 0);
    gemm_kernel<<<gg, 256>>>(x, w_ih, b_ih, b_hh, noise_in, 1);
    recur_kernel<<<128, 256>>>(w_hh, noise_h, mask, out, hn, 1);
}